// round 1
// baseline (speedup 1.0000x reference)
#include <cuda_runtime.h>
#include <cstdint>
#include <math.h>

// Problem dims
#define NB   64      // batch
#define SEQ  512     // timesteps
#define IMG  3200
#define FC   64
#define HID  256
#define G4   1024    // 4*HID

// Output layout (floats): [logprobs 64*512*2 | output_feats 64*512*256 | selected 64*256]
#define OFF_LP  0
#define OFF_OF  (NB*SEQ*2)                 // 65536
#define OFF_SEL (OFF_OF + NB*SEQ*HID)      // 8454144

// ---------------- scratch (device globals; no allocations allowed) ----------------
__device__ float g_emb[NB * FC];
__device__ float g_fuse[NB * SEQ * FC];    // (n, L, 64)

// ---------------- helpers ----------------
__device__ __forceinline__ float2 ffma2(float2 a, float2 b, float2 c) {
    unsigned long long ua = *reinterpret_cast<unsigned long long*>(&a);
    unsigned long long ub = *reinterpret_cast<unsigned long long*>(&b);
    unsigned long long uc = *reinterpret_cast<unsigned long long*>(&c);
    unsigned long long ud;
    asm("fma.rn.f32x2 %0, %1, %2, %3;" : "=l"(ud) : "l"(ua), "l"(ub), "l"(uc));
    return *reinterpret_cast<float2*>(&ud);
}

__device__ __forceinline__ uint32_t smem_u32(const void* p) {
    uint32_t a;
    asm("{ .reg .u64 t; cvta.to.shared.u64 t, %1; cvt.u32.u64 %0, t; }" : "=r"(a) : "l"(p));
    return a;
}

__device__ __forceinline__ float sigm(float x)  { return 1.0f / (1.0f + expf(-x)); }
__device__ __forceinline__ float tanh_(float x) { return 1.0f - 2.0f / (expf(2.0f * x) + 1.0f); }

// ---------------- kernel 1: emb = relu(phrase_emb @ W_phr + b_phr) ----------------
__global__ void emb_kernel(const float* __restrict__ phr,
                           const float* __restrict__ Wp,
                           const float* __restrict__ bp) {
    __shared__ float ps[304];
    int b = blockIdx.x, tid = threadIdx.x;   // 64 threads
    for (int i = tid; i < 300; i += 64) ps[i] = phr[b * 300 + i];
    __syncthreads();
    float acc = bp[tid];
#pragma unroll 4
    for (int k = 0; k < 300; k++) acc += ps[k] * Wp[k * 64 + tid];
    g_emb[b * 64 + tid] = fmaxf(acc, 0.0f);
}

// ---------------- kernel 2: fuse = relu(img @ W_cnn + b_cnn) * emb ----------------
// M=32768 (n*L), K=3200, N=64. Block tile 128x64, 256 threads, thread tile 8x4, f32x2 FMA.
__global__ __launch_bounds__(256) void fuse_kernel(const float* __restrict__ img,
                                                   const float* __restrict__ Wc,
                                                   const float* __restrict__ bc) {
    __shared__ float As[2][16][132];
    __shared__ float Bs[2][16][64];
    __shared__ float es[64];

    const int tid = threadIdx.x;
    const int tx = tid & 15, ty = tid >> 4;
    const int row0 = blockIdx.x * 128;
    const int batch = row0 >> 9;             // 512 rows per batch, tiles never straddle

    if (tid < 64) es[tid] = g_emb[batch * 64 + tid];

    float bcr[4];
#pragma unroll
    for (int c = 0; c < 4; c++) bcr[c] = bc[tx * 4 + c];

    float2 acc[4][4];
#pragma unroll
    for (int mp = 0; mp < 4; mp++)
#pragma unroll
        for (int c = 0; c < 4; c++) acc[mp][c] = make_float2(0.f, 0.f);

    auto loadA = [&](int s, int kk) {
#pragma unroll
        for (int i = 0; i < 2; i++) {
            int id = tid * 2 + i;
            int m = id >> 2, q = id & 3;
            float4 v = *reinterpret_cast<const float4*>(img + (size_t)(row0 + m) * IMG + kk + q * 4);
            As[s][q * 4 + 0][m] = v.x;
            As[s][q * 4 + 1][m] = v.y;
            As[s][q * 4 + 2][m] = v.z;
            As[s][q * 4 + 3][m] = v.w;
        }
    };
    auto loadB = [&](int s, int kk) {
        int k = tid >> 4, q = tid & 15;
        *reinterpret_cast<float4*>(&Bs[s][k][q * 4]) =
            *reinterpret_cast<const float4*>(Wc + (size_t)(kk + k) * 64 + q * 4);
    };

    loadA(0, 0);
    loadB(0, 0);
    __syncthreads();

    for (int ch = 0; ch < 200; ch++) {
        int s = ch & 1;
        if (ch + 1 < 200) { loadA(s ^ 1, (ch + 1) * 16); loadB(s ^ 1, (ch + 1) * 16); }
#pragma unroll
        for (int k = 0; k < 16; k++) {
            float4 b4 = *reinterpret_cast<const float4*>(&Bs[s][k][tx * 4]);
            float4 a0 = *reinterpret_cast<const float4*>(&As[s][k][ty * 8]);
            float4 a1 = *reinterpret_cast<const float4*>(&As[s][k][ty * 8 + 4]);
            float2 aa[4] = { {a0.x, a0.y}, {a0.z, a0.w}, {a1.x, a1.y}, {a1.z, a1.w} };
            float  bb[4] = { b4.x, b4.y, b4.z, b4.w };
#pragma unroll
            for (int c = 0; c < 4; c++) {
                float2 bv = make_float2(bb[c], bb[c]);
#pragma unroll
                for (int mp = 0; mp < 4; mp++) acc[mp][c] = ffma2(aa[mp], bv, acc[mp][c]);
            }
        }
        __syncthreads();
    }

    float sc[4];
#pragma unroll
    for (int c = 0; c < 4; c++) sc[c] = es[tx * 4 + c];

#pragma unroll
    for (int mp = 0; mp < 4; mp++) {
        float4 r0v, r1v;
        r0v.x = fmaxf(acc[mp][0].x + bcr[0], 0.f) * sc[0];
        r0v.y = fmaxf(acc[mp][1].x + bcr[1], 0.f) * sc[1];
        r0v.z = fmaxf(acc[mp][2].x + bcr[2], 0.f) * sc[2];
        r0v.w = fmaxf(acc[mp][3].x + bcr[3], 0.f) * sc[3];
        r1v.x = fmaxf(acc[mp][0].y + bcr[0], 0.f) * sc[0];
        r1v.y = fmaxf(acc[mp][1].y + bcr[1], 0.f) * sc[1];
        r1v.z = fmaxf(acc[mp][2].y + bcr[2], 0.f) * sc[2];
        r1v.w = fmaxf(acc[mp][3].y + bcr[3], 0.f) * sc[3];
        int r = row0 + ty * 8 + mp * 2;
        *reinterpret_cast<float4*>(g_fuse + (size_t)r * 64 + tx * 4)       = r0v;
        *reinterpret_cast<float4*>(g_fuse + (size_t)(r + 1) * 64 + tx * 4) = r1v;
    }
}

// ---------------- kernel 3: LSTM over 512 steps ----------------
// 16 clusters x 8 CTAs. Each cluster owns 4 batch elements. Each CTA owns 32 hidden
// units (all 4 gate types = 128 gate columns) with its W_hh/W_ih slices resident in
// smem. h is exchanged per step via DSMEM stores + one cluster.sync.
__global__ void __cluster_dims__(8, 1, 1) __launch_bounds__(256, 1)
lstm_kernel(const float* __restrict__ Whh, const float* __restrict__ Wih,
            const float* __restrict__ bih, const float* __restrict__ bhh,
            float* __restrict__ of /* output_feats (n,L,256) */) {
    extern __shared__ float sm[];
    float* Wh   = sm;            // 256*128
    float* Wi   = Wh + 32768;    // 64*128
    float* bias = Wi + 8192;     // 128
    float* hbuf = bias + 128;    // 2 * 256*4
    float* xbuf = hbuf + 2048;   // 2 * 64*4
    float* gsm  = xbuf + 512;    // 128*4

    const int tid = threadIdx.x;                 // 256 threads
    const int rank = blockIdx.x & 7;             // rank within cluster
    const int batch0 = (blockIdx.x >> 3) * 4;

    // Load weight slices: gate slot g in [0,128): type=g>>5, unit=rank*32+(g&31)
    for (int idx = tid; idx < 32768; idx += 256) {
        int k = idx >> 7, g = idx & 127;
        int col = ((g >> 5) << 8) + (rank << 5) + (g & 31);
        Wh[idx] = Whh[k * G4 + col];
    }
    for (int idx = tid; idx < 8192; idx += 256) {
        int k = idx >> 7, g = idx & 127;
        int col = ((g >> 5) << 8) + (rank << 5) + (g & 31);
        Wi[idx] = Wih[k * G4 + col];
    }
    if (tid < 128) {
        int g = tid;
        int col = ((g >> 5) << 8) + (rank << 5) + (g & 31);
        bias[g] = bih[col] + bhh[col];
    }
    // zero ONLY buffer 0 of h (peers may already be writing buffer 1 via DSMEM)
    for (int idx = tid; idx < 1024; idx += 256) hbuf[idx] = 0.0f;
    // x for t=0 into buffer 0
    {
        int b = tid >> 6, k = tid & 63;
        xbuf[(k << 2) + b] = g_fuse[(size_t)(batch0 + b) * (SEQ * FC) + k];
    }
    __syncthreads();

    const int g  = tid >> 1;     // gate slot 0..127
    const int bp = tid & 1;      // batch pair 0/1
    float creg = 0.0f;           // c for (tid<128): batch=tid>>5, unit local=tid&31
    int p = 0;

    for (int t = 0; t < SEQ; t++) {
        // ---- gate GEMM: gates[g][4 batches], each thread 1 gate x 2 batches ----
        float acc0 = bias[g], acc1 = acc0;
        const float* hp = hbuf + (p ? 1024 : 0);
        const float* wr = Wh + g;
#pragma unroll 8
        for (int k = 0; k < HID; k++) {
            float w = wr[k << 7];
            float2 h2 = *reinterpret_cast<const float2*>(hp + (k << 2) + (bp << 1));
            acc0 += w * h2.x;
            acc1 += w * h2.y;
        }
        const float* xp = xbuf + (p ? 256 : 0);
        const float* wi = Wi + g;
#pragma unroll 8
        for (int k = 0; k < FC; k++) {
            float w = wi[k << 7];
            float2 x2 = *reinterpret_cast<const float2*>(xp + (k << 2) + (bp << 1));
            acc0 += w * x2.x;
            acc1 += w * x2.y;
        }
        gsm[(g << 2) + (bp << 1)]     = acc0;
        gsm[(g << 2) + (bp << 1) + 1] = acc1;
        __syncthreads();

        // ---- state update + h broadcast ----
        if (tid < 128) {
            int b = tid >> 5, j = tid & 31;
            float gi = gsm[(j << 2) + b];
            float gf = gsm[((32 + j) << 2) + b];
            float gg = gsm[((64 + j) << 2) + b];
            float go = gsm[((96 + j) << 2) + b];
            float tg = tanh_(gg);
            creg = sigm(gf) * creg + sigm(gi) * tg;
            float h = sigm(go) * tanh_(creg);
            of[(size_t)(batch0 + b) * (SEQ * HID) + (size_t)t * HID + (rank << 5) + j] = h;
            // broadcast h to all 8 CTAs' next h buffer
            uint32_t loff = smem_u32(hbuf + ((p ^ 1) ? 1024 : 0) + ((((rank << 5) + j) << 2) + b));
#pragma unroll
            for (int r = 0; r < 8; r++) {
                uint32_t ra;
                asm("mapa.shared::cluster.u32 %0, %1, %2;" : "=r"(ra) : "r"(loff), "r"(r));
                asm volatile("st.shared::cluster.f32 [%0], %1;" :: "r"(ra), "f"(h));
            }
        } else if (t + 1 < SEQ) {
            // other half of the CTA prefetches x for t+1
            int idx = tid - 128;
#pragma unroll
            for (int i = 0; i < 2; i++) {
                int e = idx + (i << 7);
                int b = e >> 6, k = e & 63;
                xbuf[((p ^ 1) ? 256 : 0) + (k << 2) + b] =
                    g_fuse[(size_t)(batch0 + b) * (SEQ * FC) + (size_t)(t + 1) * FC + k];
            }
        }
        asm volatile("barrier.cluster.arrive.aligned;" ::: "memory");
        asm volatile("barrier.cluster.wait.aligned;"   ::: "memory");
        p ^= 1;
    }
}

// ---------------- kernel 4: classifier + log_softmax ----------------
// hid = relu(of @ W_c1 + b_c1); logits = hid @ W_c2 + b_c2; logprobs.
__global__ __launch_bounds__(256) void cls_kernel(const float* __restrict__ of,
                                                  const float* __restrict__ W1,
                                                  const float* __restrict__ b1,
                                                  const float* __restrict__ W2,
                                                  const float* __restrict__ b2,
                                                  float* __restrict__ lp) {
    __shared__ float As[2][16][132];
    __shared__ float Bs[2][16][64];

    const int tid = threadIdx.x;
    const int tx = tid & 15, ty = tid >> 4;
    const int row0 = blockIdx.x * 128;

    float b1r[4], w20[4], w21[4];
#pragma unroll
    for (int c = 0; c < 4; c++) {
        int f = tx * 4 + c;
        b1r[c] = b1[f];
        w20[c] = W2[f * 2 + 0];
        w21[c] = W2[f * 2 + 1];
    }
    const float bb0 = b2[0], bb1 = b2[1];

    float2 acc[4][4];
#pragma unroll
    for (int mp = 0; mp < 4; mp++)
#pragma unroll
        for (int c = 0; c < 4; c++) acc[mp][c] = make_float2(0.f, 0.f);

    auto loadA = [&](int s, int kk) {
#pragma unroll
        for (int i = 0; i < 2; i++) {
            int id = tid * 2 + i;
            int m = id >> 2, q = id & 3;
            float4 v = *reinterpret_cast<const float4*>(of + (size_t)(row0 + m) * HID + kk + q * 4);
            As[s][q * 4 + 0][m] = v.x;
            As[s][q * 4 + 1][m] = v.y;
            As[s][q * 4 + 2][m] = v.z;
            As[s][q * 4 + 3][m] = v.w;
        }
    };
    auto loadB = [&](int s, int kk) {
        int k = tid >> 4, q = tid & 15;
        *reinterpret_cast<float4*>(&Bs[s][k][q * 4]) =
            *reinterpret_cast<const float4*>(W1 + (size_t)(kk + k) * 64 + q * 4);
    };

    loadA(0, 0);
    loadB(0, 0);
    __syncthreads();

    for (int ch = 0; ch < 16; ch++) {
        int s = ch & 1;
        if (ch + 1 < 16) { loadA(s ^ 1, (ch + 1) * 16); loadB(s ^ 1, (ch + 1) * 16); }
#pragma unroll
        for (int k = 0; k < 16; k++) {
            float4 b4 = *reinterpret_cast<const float4*>(&Bs[s][k][tx * 4]);
            float4 a0 = *reinterpret_cast<const float4*>(&As[s][k][ty * 8]);
            float4 a1 = *reinterpret_cast<const float4*>(&As[s][k][ty * 8 + 4]);
            float2 aa[4] = { {a0.x, a0.y}, {a0.z, a0.w}, {a1.x, a1.y}, {a1.z, a1.w} };
            float  bb[4] = { b4.x, b4.y, b4.z, b4.w };
#pragma unroll
            for (int c = 0; c < 4; c++) {
                float2 bv = make_float2(bb[c], bb[c]);
#pragma unroll
                for (int mp = 0; mp < 4; mp++) acc[mp][c] = ffma2(aa[mp], bv, acc[mp][c]);
            }
        }
        __syncthreads();
    }

    // per-row: relu+bias, dot with W_c2 columns, reduce across the 16 tx lanes
#pragma unroll
    for (int mp = 0; mp < 4; mp++) {
#pragma unroll
        for (int half = 0; half < 2; half++) {
            float p0 = 0.f, p1 = 0.f;
#pragma unroll
            for (int c = 0; c < 4; c++) {
                float v = half ? acc[mp][c].y : acc[mp][c].x;
                float hd = fmaxf(v + b1r[c], 0.f);
                p0 += hd * w20[c];
                p1 += hd * w21[c];
            }
#pragma unroll
            for (int s = 1; s < 16; s <<= 1) {
                p0 += __shfl_xor_sync(0xffffffffu, p0, s);
                p1 += __shfl_xor_sync(0xffffffffu, p1, s);
            }
            if ((tid & 15) == 0) {
                float l0 = p0 + bb0, l1 = p1 + bb1;
                float m = fmaxf(l0, l1);
                float lse = m + logf(expf(l0 - m) + expf(l1 - m));
                int row = row0 + ty * 8 + mp * 2 + half;
                lp[row * 2 + 0] = l0 - lse;
                lp[row * 2 + 1] = l1 - lse;
            }
        }
    }
}

// ---------------- kernel 5: gather selected = output_feats[b, select_ixs[b], :] ----
__global__ void sel_kernel(const int* __restrict__ ix, const float* __restrict__ of,
                           float* __restrict__ sel) {
    int b = blockIdx.x;
    int t = ix[b];
    sel[b * HID + threadIdx.x] = of[(size_t)b * (SEQ * HID) + (size_t)t * HID + threadIdx.x];
}

// ---------------- launch ----------------
extern "C" void kernel_launch(void* const* d_in, const int* in_sizes, int n_in,
                              void* d_out, int out_size) {
    const float* img = (const float*)d_in[0];
    const float* phr = (const float*)d_in[1];
    /* d_in[2] masks: unused (as in reference) */
    const int*   six = (const int*)d_in[3];
    const float* Wc  = (const float*)d_in[4];
    const float* bc  = (const float*)d_in[5];
    const float* Wp  = (const float*)d_in[6];
    const float* bp  = (const float*)d_in[7];
    const float* Wih = (const float*)d_in[8];
    const float* bih = (const float*)d_in[9];
    const float* Whh = (const float*)d_in[10];
    const float* bhh = (const float*)d_in[11];
    const float* W1  = (const float*)d_in[12];
    const float* b1  = (const float*)d_in[13];
    const float* W2  = (const float*)d_in[14];
    const float* b2  = (const float*)d_in[15];

    float* out = (float*)d_out;
    float* lp  = out + OFF_LP;
    float* of  = out + OFF_OF;
    float* sel = out + OFF_SEL;

    cudaFuncSetAttribute(lstm_kernel, cudaFuncAttributeMaxDynamicSharedMemorySize, 176640);

    emb_kernel <<<64, 64>>>(phr, Wp, bp);
    fuse_kernel<<<256, 256>>>(img, Wc, bc);
    lstm_kernel<<<128, 256, 176640>>>(Whh, Wih, bih, bhh, of);
    cls_kernel <<<256, 256>>>(of, W1, b1, W2, b2, lp);
    sel_kernel <<<64, 256>>>(six, of, sel);
}

// round 2
// speedup vs baseline: 2.1620x; 2.1620x over previous
#include <cuda_runtime.h>
#include <cstdint>
#include <math.h>

// Problem dims
#define NB   64      // batch
#define SEQ  512     // timesteps
#define IMG  3200
#define FC   64
#define HID  256
#define G4   1024    // 4*HID

// Output layout (floats): [logprobs 64*512*2 | output_feats 64*512*256 | selected 64*256]
#define OFF_LP  0
#define OFF_OF  (NB*SEQ*2)
#define OFF_SEL (OFF_OF + NB*SEQ*HID)

// ---------------- scratch (device globals; no allocations allowed) ----------------
__device__ float g_emb[NB * FC];
__device__ float g_fuse[NB * SEQ * FC];              // (n, L, 64)
__device__ float g_gx[(size_t)NB * SEQ * G4];        // gates_x: [row = n*512+l][1024]

// ---------------- helpers ----------------
__device__ __forceinline__ float2 ffma2(float2 a, float2 b, float2 c) {
    unsigned long long ua = *reinterpret_cast<unsigned long long*>(&a);
    unsigned long long ub = *reinterpret_cast<unsigned long long*>(&b);
    unsigned long long uc = *reinterpret_cast<unsigned long long*>(&c);
    unsigned long long ud;
    asm("fma.rn.f32x2 %0, %1, %2, %3;" : "=l"(ud) : "l"(ua), "l"(ub), "l"(uc));
    return *reinterpret_cast<float2*>(&ud);
}

__device__ __forceinline__ uint32_t smem_u32(const void* p) {
    uint32_t a;
    asm("{ .reg .u64 t; cvta.to.shared.u64 t, %1; cvt.u32.u64 %0, t; }" : "=r"(a) : "l"(p));
    return a;
}

__device__ __forceinline__ float sigm(float x)  { return 1.0f / (1.0f + __expf(-x)); }
__device__ __forceinline__ float tanh_(float x) { return 1.0f - 2.0f / (__expf(2.0f * x) + 1.0f); }

__device__ __forceinline__ void mbar_init(uint32_t a, uint32_t c) {
    asm volatile("mbarrier.init.shared.b64 [%0], %1;" :: "r"(a), "r"(c) : "memory");
}
__device__ __forceinline__ void mbar_expect_tx(uint32_t a, uint32_t tx) {
    asm volatile("mbarrier.arrive.expect_tx.shared.b64 _, [%0], %1;" :: "r"(a), "r"(tx) : "memory");
}
__device__ __forceinline__ void mbar_wait(uint32_t a, uint32_t phase) {
    asm volatile(
        "{\n\t"
        ".reg .pred P;\n\t"
        "WL_%=:\n\t"
        "mbarrier.try_wait.parity.acquire.cta.shared::cta.b64 P, [%0], %1, 0x989680;\n\t"
        "@P bra WD_%=;\n\t"
        "bra WL_%=;\n\t"
        "WD_%=:\n\t"
        "}" :: "r"(a), "r"(phase) : "memory");
}
__device__ __forceinline__ uint32_t mapa_u32(uint32_t a, uint32_t r) {
    uint32_t ra;
    asm("mapa.shared::cluster.u32 %0, %1, %2;" : "=r"(ra) : "r"(a), "r"(r));
    return ra;
}
__device__ __forceinline__ void st_async_f32(uint32_t dst, float v, uint32_t rbar) {
    asm volatile("st.async.shared::cluster.mbarrier::complete_tx::bytes.b32 [%0], %1, [%2];"
                 :: "r"(dst), "r"(__float_as_uint(v)), "r"(rbar) : "memory");
}

// ---------------- kernel 1: emb = relu(phrase_emb @ W_phr + b_phr) ----------------
__global__ void emb_kernel(const float* __restrict__ phr,
                           const float* __restrict__ Wp,
                           const float* __restrict__ bp) {
    __shared__ float ps[304];
    int b = blockIdx.x, tid = threadIdx.x;
    for (int i = tid; i < 300; i += 64) ps[i] = phr[b * 300 + i];
    __syncthreads();
    float acc = bp[tid];
#pragma unroll 4
    for (int k = 0; k < 300; k++) acc += ps[k] * Wp[k * 64 + tid];
    g_emb[b * 64 + tid] = fmaxf(acc, 0.0f);
}

// ---------------- kernel 2: fuse = relu(img @ W_cnn + b_cnn) * emb ----------------
__global__ __launch_bounds__(256) void fuse_kernel(const float* __restrict__ img,
                                                   const float* __restrict__ Wc,
                                                   const float* __restrict__ bc) {
    __shared__ float As[2][16][132];
    __shared__ float Bs[2][16][64];
    __shared__ float es[64];

    const int tid = threadIdx.x;
    const int tx = tid & 15, ty = tid >> 4;
    const int row0 = blockIdx.x * 128;
    const int batch = row0 >> 9;

    if (tid < 64) es[tid] = g_emb[batch * 64 + tid];

    float bcr[4];
#pragma unroll
    for (int c = 0; c < 4; c++) bcr[c] = bc[tx * 4 + c];

    float2 acc[4][4];
#pragma unroll
    for (int mp = 0; mp < 4; mp++)
#pragma unroll
        for (int c = 0; c < 4; c++) acc[mp][c] = make_float2(0.f, 0.f);

    auto loadA = [&](int s, int kk) {
#pragma unroll
        for (int i = 0; i < 2; i++) {
            int id = tid * 2 + i;
            int m = id >> 2, q = id & 3;
            float4 v = *reinterpret_cast<const float4*>(img + (size_t)(row0 + m) * IMG + kk + q * 4);
            As[s][q * 4 + 0][m] = v.x;
            As[s][q * 4 + 1][m] = v.y;
            As[s][q * 4 + 2][m] = v.z;
            As[s][q * 4 + 3][m] = v.w;
        }
    };
    auto loadB = [&](int s, int kk) {
        int k = tid >> 4, q = tid & 15;
        *reinterpret_cast<float4*>(&Bs[s][k][q * 4]) =
            *reinterpret_cast<const float4*>(Wc + (size_t)(kk + k) * 64 + q * 4);
    };

    loadA(0, 0);
    loadB(0, 0);
    __syncthreads();

    for (int ch = 0; ch < 200; ch++) {
        int s = ch & 1;
        if (ch + 1 < 200) { loadA(s ^ 1, (ch + 1) * 16); loadB(s ^ 1, (ch + 1) * 16); }
#pragma unroll
        for (int k = 0; k < 16; k++) {
            float4 b4 = *reinterpret_cast<const float4*>(&Bs[s][k][tx * 4]);
            float4 a0 = *reinterpret_cast<const float4*>(&As[s][k][ty * 8]);
            float4 a1 = *reinterpret_cast<const float4*>(&As[s][k][ty * 8 + 4]);
            float2 aa[4] = { {a0.x, a0.y}, {a0.z, a0.w}, {a1.x, a1.y}, {a1.z, a1.w} };
            float  bb[4] = { b4.x, b4.y, b4.z, b4.w };
#pragma unroll
            for (int c = 0; c < 4; c++) {
                float2 bv = make_float2(bb[c], bb[c]);
#pragma unroll
                for (int mp = 0; mp < 4; mp++) acc[mp][c] = ffma2(aa[mp], bv, acc[mp][c]);
            }
        }
        __syncthreads();
    }

    float sc[4];
#pragma unroll
    for (int c = 0; c < 4; c++) sc[c] = es[tx * 4 + c];

#pragma unroll
    for (int mp = 0; mp < 4; mp++) {
        float4 r0v, r1v;
        r0v.x = fmaxf(acc[mp][0].x + bcr[0], 0.f) * sc[0];
        r0v.y = fmaxf(acc[mp][1].x + bcr[1], 0.f) * sc[1];
        r0v.z = fmaxf(acc[mp][2].x + bcr[2], 0.f) * sc[2];
        r0v.w = fmaxf(acc[mp][3].x + bcr[3], 0.f) * sc[3];
        r1v.x = fmaxf(acc[mp][0].y + bcr[0], 0.f) * sc[0];
        r1v.y = fmaxf(acc[mp][1].y + bcr[1], 0.f) * sc[1];
        r1v.z = fmaxf(acc[mp][2].y + bcr[2], 0.f) * sc[2];
        r1v.w = fmaxf(acc[mp][3].y + bcr[3], 0.f) * sc[3];
        int r = row0 + ty * 8 + mp * 2;
        *reinterpret_cast<float4*>(g_fuse + (size_t)r * 64 + tx * 4)       = r0v;
        *reinterpret_cast<float4*>(g_fuse + (size_t)(r + 1) * 64 + tx * 4) = r1v;
    }
}

// ---------------- kernel 2b: gx = fuse @ W_ih + (b_ih + b_hh) ----------------
// M=32768, K=64, N=1024. Grid (256, 16): block = 128 rows x 64 cols.
__global__ __launch_bounds__(256) void gx_kernel(const float* __restrict__ Wih,
                                                 const float* __restrict__ bih,
                                                 const float* __restrict__ bhh) {
    __shared__ float As[2][16][132];
    __shared__ float Bs[2][16][64];

    const int tid = threadIdx.x;
    const int tx = tid & 15, ty = tid >> 4;
    const int row0 = blockIdx.x * 128;
    const int n0 = blockIdx.y * 64;

    float bsr[4];
#pragma unroll
    for (int c = 0; c < 4; c++) bsr[c] = bih[n0 + tx * 4 + c] + bhh[n0 + tx * 4 + c];

    float2 acc[4][4];
#pragma unroll
    for (int mp = 0; mp < 4; mp++)
#pragma unroll
        for (int c = 0; c < 4; c++) acc[mp][c] = make_float2(0.f, 0.f);

    auto loadA = [&](int s, int kk) {
#pragma unroll
        for (int i = 0; i < 2; i++) {
            int id = tid * 2 + i;
            int m = id >> 2, q = id & 3;
            float4 v = *reinterpret_cast<const float4*>(g_fuse + (size_t)(row0 + m) * FC + kk + q * 4);
            As[s][q * 4 + 0][m] = v.x;
            As[s][q * 4 + 1][m] = v.y;
            As[s][q * 4 + 2][m] = v.z;
            As[s][q * 4 + 3][m] = v.w;
        }
    };
    auto loadB = [&](int s, int kk) {
        int k = tid >> 4, q = tid & 15;
        *reinterpret_cast<float4*>(&Bs[s][k][q * 4]) =
            *reinterpret_cast<const float4*>(Wih + (size_t)(kk + k) * G4 + n0 + q * 4);
    };

    loadA(0, 0);
    loadB(0, 0);
    __syncthreads();

    for (int ch = 0; ch < 4; ch++) {
        int s = ch & 1;
        if (ch + 1 < 4) { loadA(s ^ 1, (ch + 1) * 16); loadB(s ^ 1, (ch + 1) * 16); }
#pragma unroll
        for (int k = 0; k < 16; k++) {
            float4 b4 = *reinterpret_cast<const float4*>(&Bs[s][k][tx * 4]);
            float4 a0 = *reinterpret_cast<const float4*>(&As[s][k][ty * 8]);
            float4 a1 = *reinterpret_cast<const float4*>(&As[s][k][ty * 8 + 4]);
            float2 aa[4] = { {a0.x, a0.y}, {a0.z, a0.w}, {a1.x, a1.y}, {a1.z, a1.w} };
            float  bb[4] = { b4.x, b4.y, b4.z, b4.w };
#pragma unroll
            for (int c = 0; c < 4; c++) {
                float2 bv = make_float2(bb[c], bb[c]);
#pragma unroll
                for (int mp = 0; mp < 4; mp++) acc[mp][c] = ffma2(aa[mp], bv, acc[mp][c]);
            }
        }
        __syncthreads();
    }

#pragma unroll
    for (int mp = 0; mp < 4; mp++) {
        float4 r0v, r1v;
        r0v.x = acc[mp][0].x + bsr[0]; r0v.y = acc[mp][1].x + bsr[1];
        r0v.z = acc[mp][2].x + bsr[2]; r0v.w = acc[mp][3].x + bsr[3];
        r1v.x = acc[mp][0].y + bsr[0]; r1v.y = acc[mp][1].y + bsr[1];
        r1v.z = acc[mp][2].y + bsr[2]; r1v.w = acc[mp][3].y + bsr[3];
        int r = row0 + ty * 8 + mp * 2;
        *reinterpret_cast<float4*>(g_gx + (size_t)r * G4 + n0 + tx * 4)       = r0v;
        *reinterpret_cast<float4*>(g_gx + (size_t)(r + 1) * G4 + n0 + tx * 4) = r1v;
    }
}

// ---------------- kernel 3: LSTM over 512 steps ----------------
// 16 clusters x 8 CTAs, 512 threads. Thread = (gate g in [0,128), quarter q in [0,4)).
// W_hh slice lives in REGISTERS (64 floats / thread). h exchanged per step via
// st.async -> peer mbarrier (expect_tx 4096 B), double-buffered.
#define PADQ 68
#define HBUF_BYTES (4 * 4 * PADQ * 4)   // one buffer: [4 b][4 q][68] floats = 4352 B

__global__ void __cluster_dims__(8, 1, 1) __launch_bounds__(512, 1)
lstm_kernel(const float* __restrict__ Whh,
            const float* __restrict__ gx,
            float* __restrict__ of) {
    __shared__ __align__(16) float hbuf[2][4][4][PADQ];   // [buf][b][q][64(+4)]
    __shared__ __align__(16) float gxs[2][4][128];        // [buf][b][gate-local]
    __shared__ __align__(16) float gsm[128][4];           // [gate-local][b]
    __shared__ __align__(8)  unsigned long long bars[2];

    const int tid  = threadIdx.x;
    const int warp = tid >> 5, lane = tid & 31;
    const int gl = lane & 7, q = lane >> 3;
    const int g  = warp * 8 + gl;          // gate slot 0..127
    const int rank   = blockIdx.x & 7;
    const int batch0 = (blockIdx.x >> 3) * 4;
    const int col = ((g >> 5) << 8) + (rank << 5) + (g & 31);  // column in [0,1024)

    // ---- W_hh registers: k in [q*64, q*64+64), packed as 32 float2 ----
    float2 Wr[32];
    {
        const float* wp = Whh + (size_t)(q * 64) * G4 + col;
#pragma unroll
        for (int j = 0; j < 32; j++) {
            Wr[j].x = wp[(size_t)(2 * j) * G4];
            Wr[j].y = wp[(size_t)(2 * j + 1) * G4];
        }
    }

    const uint32_t bar0 = smem_u32(&bars[0]);
    if (tid == 0) {
        mbar_init(bar0, 1);
        mbar_init(bar0 + 8, 1);
        mbar_expect_tx(bar0, 4096);       // armed for first use (t=2)
        mbar_expect_tx(bar0 + 8, 4096);   // armed for first use (t=1)
    }
    // prefetch gx for t=0 into gxs[0]
    if (tid < 128) {
        int b = tid >> 5, ty4 = (tid >> 3) & 3, j = tid & 7;
        const float* gp = gx + ((size_t)(batch0 + b) * SEQ + 0) * G4 + ty4 * 256 + rank * 32 + j * 4;
        *reinterpret_cast<float4*>(&gxs[0][b][ty4 * 32 + j * 4]) =
            *reinterpret_cast<const float4*>(gp);
    }
    __syncthreads();
    asm volatile("barrier.cluster.arrive.aligned;" ::: "memory");
    asm volatile("barrier.cluster.wait.aligned;"   ::: "memory");

    // producer identity (threads 0..127): batch bb, unit ub
    const int bb = tid >> 5, ub = tid & 31;
    const int kglob = (rank << 5) + ub;
    uint32_t dst_loc0 = 0, barloc = bar0;
    if (tid < 128)
        dst_loc0 = smem_u32(&hbuf[0][bb][kglob >> 6][kglob & 63]);

    float creg = 0.0f;
    int ph0 = 0, ph1 = 0;

    for (int t = 0; t < SEQ; t++) {
        const int p = t & 1;
        float val[4];

        if (t > 0) {
            uint32_t barp = bar0 + p * 8;
            int par = p ? ph1 : ph0;
            mbar_wait(barp, par);
            if (p) ph1 ^= 1; else ph0 ^= 1;
            if (tid == 0) mbar_expect_tx(barp, 4096);   // re-arm for t+2

            // ---- recurrent GEMM: val[b] = sum_k W[g][k] * h[b][k], k in quarter q ----
#pragma unroll
            for (int b = 0; b < 4; b++) {
                float2 acc = make_float2(0.f, 0.f);
                const float* hp = &hbuf[p][b][q][0];
#pragma unroll
                for (int j = 0; j < 16; j++) {
                    float4 h4 = *reinterpret_cast<const float4*>(hp + j * 4);
                    acc = ffma2(Wr[2 * j],     make_float2(h4.x, h4.y), acc);
                    acc = ffma2(Wr[2 * j + 1], make_float2(h4.z, h4.w), acc);
                }
                val[b] = acc.x + acc.y;
            }
        } else {
#pragma unroll
            for (int b = 0; b < 4; b++) val[b] = 0.0f;
        }

        // reduce across quarters (lanes differing in bits 3,4)
#pragma unroll
        for (int b = 0; b < 4; b++) {
            val[b] += __shfl_xor_sync(0xffffffffu, val[b], 8);
            val[b] += __shfl_xor_sync(0xffffffffu, val[b], 16);
        }
        if (lane < 8) {
            float4 v = make_float4(val[0], val[1], val[2], val[3]);
            *reinterpret_cast<float4*>(&gsm[warp * 8 + lane][0]) = v;
        }
        __syncthreads();

        if (tid < 128) {
            // activation + state update for (batch bb, unit ub)
            float gi = gsm[ub][bb]       + gxs[p][bb][ub];
            float gf = gsm[32 + ub][bb]  + gxs[p][bb][32 + ub];
            float gg = gsm[64 + ub][bb]  + gxs[p][bb][64 + ub];
            float go = gsm[96 + ub][bb]  + gxs[p][bb][96 + ub];
            float tg = tanh_(gg);
            creg = sigm(gf) * creg + sigm(gi) * tg;
            float h = sigm(go) * tanh_(creg);

            if (t + 1 < SEQ) {
                uint32_t doff = dst_loc0 + (p ^ 1) * HBUF_BYTES;
                uint32_t boff = barloc + (p ^ 1) * 8;
#pragma unroll
                for (int r = 0; r < 8; r++) {
                    uint32_t rd = mapa_u32(doff, r);
                    uint32_t rb = mapa_u32(boff, r);
                    st_async_f32(rd, h, rb);
                }
            }
            of[(size_t)(batch0 + bb) * (SEQ * HID) + (size_t)t * HID + (rank << 5) + ub] = h;
        } else if (tid < 256 && t + 1 < SEQ) {
            // prefetch gx for t+1
            int i = tid - 128;
            int b = i >> 5, ty4 = (i >> 3) & 3, j = i & 7;
            const float* gp = gx + ((size_t)(batch0 + b) * SEQ + (t + 1)) * G4 + ty4 * 256 + rank * 32 + j * 4;
            *reinterpret_cast<float4*>(&gxs[p ^ 1][b][ty4 * 32 + j * 4]) =
                *reinterpret_cast<const float4*>(gp);
        }
        // no __syncthreads here: cross-step ordering is provided by the mbarrier
        // release(st.async) -> acquire(try_wait) chain plus the post-GEMM sync above.
    }

    asm volatile("barrier.cluster.arrive.aligned;" ::: "memory");
    asm volatile("barrier.cluster.wait.aligned;"   ::: "memory");
}

// ---------------- kernel 4: classifier + log_softmax ----------------
__global__ __launch_bounds__(256) void cls_kernel(const float* __restrict__ of,
                                                  const float* __restrict__ W1,
                                                  const float* __restrict__ b1,
                                                  const float* __restrict__ W2,
                                                  const float* __restrict__ b2,
                                                  float* __restrict__ lp) {
    __shared__ float As[2][16][132];
    __shared__ float Bs[2][16][64];

    const int tid = threadIdx.x;
    const int tx = tid & 15, ty = tid >> 4;
    const int row0 = blockIdx.x * 128;

    float b1r[4], w20[4], w21[4];
#pragma unroll
    for (int c = 0; c < 4; c++) {
        int f = tx * 4 + c;
        b1r[c] = b1[f];
        w20[c] = W2[f * 2 + 0];
        w21[c] = W2[f * 2 + 1];
    }
    const float bb0 = b2[0], bb1 = b2[1];

    float2 acc[4][4];
#pragma unroll
    for (int mp = 0; mp < 4; mp++)
#pragma unroll
        for (int c = 0; c < 4; c++) acc[mp][c] = make_float2(0.f, 0.f);

    auto loadA = [&](int s, int kk) {
#pragma unroll
        for (int i = 0; i < 2; i++) {
            int id = tid * 2 + i;
            int m = id >> 2, q = id & 3;
            float4 v = *reinterpret_cast<const float4*>(of + (size_t)(row0 + m) * HID + kk + q * 4);
            As[s][q * 4 + 0][m] = v.x;
            As[s][q * 4 + 1][m] = v.y;
            As[s][q * 4 + 2][m] = v.z;
            As[s][q * 4 + 3][m] = v.w;
        }
    };
    auto loadB = [&](int s, int kk) {
        int k = tid >> 4, q = tid & 15;
        *reinterpret_cast<float4*>(&Bs[s][k][q * 4]) =
            *reinterpret_cast<const float4*>(W1 + (size_t)(kk + k) * 64 + q * 4);
    };

    loadA(0, 0);
    loadB(0, 0);
    __syncthreads();

    for (int ch = 0; ch < 16; ch++) {
        int s = ch & 1;
        if (ch + 1 < 16) { loadA(s ^ 1, (ch + 1) * 16); loadB(s ^ 1, (ch + 1) * 16); }
#pragma unroll
        for (int k = 0; k < 16; k++) {
            float4 b4 = *reinterpret_cast<const float4*>(&Bs[s][k][tx * 4]);
            float4 a0 = *reinterpret_cast<const float4*>(&As[s][k][ty * 8]);
            float4 a1 = *reinterpret_cast<const float4*>(&As[s][k][ty * 8 + 4]);
            float2 aa[4] = { {a0.x, a0.y}, {a0.z, a0.w}, {a1.x, a1.y}, {a1.z, a1.w} };
            float  bb[4] = { b4.x, b4.y, b4.z, b4.w };
#pragma unroll
            for (int c = 0; c < 4; c++) {
                float2 bv = make_float2(bb[c], bb[c]);
#pragma unroll
                for (int mp = 0; mp < 4; mp++) acc[mp][c] = ffma2(aa[mp], bv, acc[mp][c]);
            }
        }
        __syncthreads();
    }

#pragma unroll
    for (int mp = 0; mp < 4; mp++) {
#pragma unroll
        for (int half = 0; half < 2; half++) {
            float p0 = 0.f, p1 = 0.f;
#pragma unroll
            for (int c = 0; c < 4; c++) {
                float v = half ? acc[mp][c].y : acc[mp][c].x;
                float hd = fmaxf(v + b1r[c], 0.f);
                p0 += hd * w20[c];
                p1 += hd * w21[c];
            }
#pragma unroll
            for (int s = 1; s < 16; s <<= 1) {
                p0 += __shfl_xor_sync(0xffffffffu, p0, s);
                p1 += __shfl_xor_sync(0xffffffffu, p1, s);
            }
            if ((tid & 15) == 0) {
                float l0 = p0 + bb0, l1 = p1 + bb1;
                float m = fmaxf(l0, l1);
                float lse = m + logf(expf(l0 - m) + expf(l1 - m));
                int row = row0 + ty * 8 + mp * 2 + half;
                lp[row * 2 + 0] = l0 - lse;
                lp[row * 2 + 1] = l1 - lse;
            }
        }
    }
}

// ---------------- kernel 5: gather selected ----------------
__global__ void sel_kernel(const int* __restrict__ ix, const float* __restrict__ of,
                           float* __restrict__ sel) {
    int b = blockIdx.x;
    int t = ix[b];
    sel[b * HID + threadIdx.x] = of[(size_t)b * (SEQ * HID) + (size_t)t * HID + threadIdx.x];
}

// ---------------- launch ----------------
extern "C" void kernel_launch(void* const* d_in, const int* in_sizes, int n_in,
                              void* d_out, int out_size) {
    const float* img = (const float*)d_in[0];
    const float* phr = (const float*)d_in[1];
    const int*   six = (const int*)d_in[3];
    const float* Wc  = (const float*)d_in[4];
    const float* bc  = (const float*)d_in[5];
    const float* Wp  = (const float*)d_in[6];
    const float* bp  = (const float*)d_in[7];
    const float* Wih = (const float*)d_in[8];
    const float* bih = (const float*)d_in[9];
    const float* Whh = (const float*)d_in[10];
    const float* bhh = (const float*)d_in[11];
    const float* W1  = (const float*)d_in[12];
    const float* b1  = (const float*)d_in[13];
    const float* W2  = (const float*)d_in[14];
    const float* b2  = (const float*)d_in[15];

    float* out = (float*)d_out;
    float* lp  = out + OFF_LP;
    float* of  = out + OFF_OF;
    float* sel = out + OFF_SEL;

    float* gxp = nullptr;
    cudaGetSymbolAddress((void**)&gxp, g_gx);

    emb_kernel <<<64, 64>>>(phr, Wp, bp);
    fuse_kernel<<<256, 256>>>(img, Wc, bc);
    gx_kernel  <<<dim3(256, 16), 256>>>(Wih, bih, bhh);
    lstm_kernel<<<128, 512>>>(Whh, gxp, of);
    cls_kernel <<<256, 256>>>(of, W1, b1, W2, b2, lp);
    sel_kernel <<<64, 256>>>(six, of, sel);
}